// round 5
// baseline (speedup 1.0000x reference)
#include <cuda_runtime.h>
#include <cuda_fp16.h>
#include <cstdint>

// ============================================================================
// BBoxHead as one fp16 legacy-HMMA GEMM (mma.sync.m16n8k16; compute_103 has no
// tcgen05). C[8192,448] = A[8192,12544] x W[448,12544]^T, fp32 acc.
//   cols 0..80   -> cls head (+b_cls):  out[m*81 + n]
//   cols 81..404 -> reg head (+b_reg):  out[8192*81 + m*324 + (n-81)]
//   cols 405..447 = zero pad (discarded)
// Round-5 change vs round-4: warp grid 2Mx8N -> 1Mx8N (8 warps, 256 threads,
// warp tile 64x56, acc=112 regs). Cuts smem fragment re-reads (A 8x-redundant
// reads stay, B redundancy 2x->1x; total reads 88KB->60KB per chunk) so the
// smem crossbar (~750 cyc/chunk) drops below the MMA floor (~896 cyc/chunk).
// ============================================================================

#define KDIM  12544
#define MDIM  8192
#define NCLS  81
#define NREG  324
#define NTOT  405
#define NPAD  448
#define BM    64
#define BK    32
#define NCHUNK 392            // 12544 / 32
#define NTHREADS 256

#define A_STAGE 4096          // 64 rows x 64B
#define B_STAGE 28672         // 448 rows x 64B
#define OFF_BIAS 0
#define OFF_A    2048
#define OFF_B    (OFF_A + 3 * A_STAGE)        // 14336
#define SMEM_TOTAL (OFF_B + 3 * B_STAGE)      // 100352

__device__ __half g_Wh[(size_t)NPAD * KDIM];  // 11.2 MB fp16 W scratch

// ---------------- helpers ----------------
__device__ __forceinline__ uint32_t smem_u32(const void* p) {
    uint32_t a;
    asm("{ .reg .u64 t; cvta.to.shared.u64 t, %1; cvt.u32.u64 %0, t; }" : "=r"(a) : "l"(p));
    return a;
}
// row-stride 64B, 4 x 16B chunks per row, rotated by row/2 so both the 16B
// store phases and ldmatrix read phases are bank-conflict-free.
__device__ __forceinline__ uint32_t swz(uint32_t row, uint32_t q) {
    return row * 64u + (((q + (row >> 1)) & 3u) << 4);
}
__device__ __forceinline__ void cpa16(uint32_t dst, const void* src) {
    asm volatile("cp.async.cg.shared.global [%0], [%1], 16;" :: "r"(dst), "l"(src) : "memory");
}
#define CP_COMMIT() asm volatile("cp.async.commit_group;" ::: "memory")
#define CP_WAIT1()  asm volatile("cp.async.wait_group 1;" ::: "memory")

__device__ __forceinline__ void ldsm4(uint32_t* r, uint32_t addr) {
    asm volatile("ldmatrix.sync.aligned.m8n8.x4.shared.b16 {%0,%1,%2,%3}, [%4];"
        : "=r"(r[0]), "=r"(r[1]), "=r"(r[2]), "=r"(r[3]) : "r"(addr));
}
__device__ __forceinline__ void ldsm2(uint32_t* r, uint32_t addr) {
    asm volatile("ldmatrix.sync.aligned.m8n8.x2.shared.b16 {%0,%1}, [%2];"
        : "=r"(r[0]), "=r"(r[1]) : "r"(addr));
}
__device__ __forceinline__ void mma16816(float* c, const uint32_t* a, const uint32_t* b) {
    asm volatile(
        "mma.sync.aligned.m16n8k16.row.col.f32.f16.f16.f32 "
        "{%0,%1,%2,%3}, {%4,%5,%6,%7}, {%8,%9}, {%0,%1,%2,%3};"
        : "+f"(c[0]), "+f"(c[1]), "+f"(c[2]), "+f"(c[3])
        : "r"(a[0]), "r"(a[1]), "r"(a[2]), "r"(a[3]), "r"(b[0]), "r"(b[1]));
}
__device__ __forceinline__ uint32_t packh2(float lo, float hi) {
    uint32_t r;
    asm("cvt.rn.f16x2.f32 %0, %1, %2;" : "=r"(r) : "f"(hi), "f"(lo));
    return r;
}

// ---------------- W fp32 -> fp16 pre-kernel (rows >= 405 zeroed) ----------------
__global__ void wconv_kernel(const float* __restrict__ Wc, const float* __restrict__ Wr) {
    int row = blockIdx.y;
    int col = (blockIdx.x * 256 + threadIdx.x) * 4;
    if (col >= KDIM) return;
    float4 v = make_float4(0.f, 0.f, 0.f, 0.f);
    if (row < NCLS)      v = *reinterpret_cast<const float4*>(Wc + (size_t)row * KDIM + col);
    else if (row < NTOT) v = *reinterpret_cast<const float4*>(Wr + (size_t)(row - NCLS) * KDIM + col);
    *reinterpret_cast<uint2*>(&g_Wh[(size_t)row * KDIM + col]) =
        make_uint2(packh2(v.x, v.y), packh2(v.z, v.w));
}

// ---------------- main GEMM kernel ----------------
__global__ __launch_bounds__(NTHREADS)
void bbox_head_mma(const float* __restrict__ A,
                   const float* __restrict__ bc,
                   const float* __restrict__ br,
                   float* __restrict__ out)
{
    extern __shared__ char smem[];
    const uint32_t sb = smem_u32(smem);
    const int tid   = threadIdx.x;
    const int lane  = tid & 31;
    const int warpN = tid >> 5;         // 0..7, 56-col slice of NPAD=448
    const int mBlock = blockIdx.x * BM;
    float* bias_sm = reinterpret_cast<float*>(smem + OFF_BIAS);

    for (int j = tid; j < NPAD; j += NTHREADS)
        bias_sm[j] = (j < NCLS) ? bc[j] : ((j < NTOT) ? br[j - NCLS] : 0.f);

    // A loader role: every thread owns one 16B chunk: row (tid>>2), q (tid&3)
    const int ar = tid >> 2;            // 0..63
    const int aq = tid & 3;
    float4 abuf0, abuf1;

    float acc[4][7][4];
    #pragma unroll
    for (int i = 0; i < 4; i++)
        #pragma unroll
        for (int j = 0; j < 7; j++)
            #pragma unroll
            for (int v = 0; v < 4; v++) acc[i][j][v] = 0.f;

#define LDG_A(K0) do { \
        const float* _p = A + (size_t)(mBlock + ar) * KDIM + (K0) + aq * 8; \
        abuf0 = *reinterpret_cast<const float4*>(_p); \
        abuf1 = *reinterpret_cast<const float4*>(_p + 4); } while (0)

#define STS_A(S) do { \
        uint4 _v = make_uint4(packh2(abuf0.x, abuf0.y), packh2(abuf0.z, abuf0.w), \
                              packh2(abuf1.x, abuf1.y), packh2(abuf1.z, abuf1.w)); \
        *reinterpret_cast<uint4*>(smem + OFF_A + (S) * A_STAGE + swz(ar, aq)) = _v; } while (0)

#define CP_B(K0, S) do { \
        _Pragma("unroll") \
        for (int _i = 0; _i < 7; _i++) { \
            int _idx = tid + _i * NTHREADS; /* 0..1791 */ \
            int _row = _idx >> 2, _q = _idx & 3; \
            cpa16(sb + OFF_B + (S) * B_STAGE + swz(_row, _q), \
                  g_Wh + (size_t)_row * KDIM + (K0) + _q * 8); } } while (0)

    // ---- prologue ----
    LDG_A(0);
    CP_B(0, 0); CP_COMMIT();
    STS_A(0);
    LDG_A(BK);
    CP_B(BK, 1); CP_COMMIT();

    // ---- main loop ----
    for (int k = 0; k < NCHUNK; k++) {
        CP_WAIT1();
        __syncthreads();

        if (k + 1 < NCHUNK) STS_A((k + 1) % 3);
        if (k + 2 < NCHUNK) { LDG_A((k + 2) * BK); CP_B((k + 2) * BK, (k + 2) % 3); }
        CP_COMMIT();

        const uint32_t aS = sb + OFF_A + (k % 3) * A_STAGE;
        const uint32_t bS = sb + OFF_B + (k % 3) * B_STAGE;

        #pragma unroll
        for (int kt = 0; kt < 2; kt++) {
            uint32_t afrag[4][4];
            #pragma unroll
            for (int msub = 0; msub < 4; msub++) {
                uint32_t row = msub * 16 + ((lane >> 3) & 1) * 8 + (lane & 7);
                uint32_t q   = kt * 2 + (lane >> 4);
                ldsm4(afrag[msub], aS + swz(row, q));
            }
            uint32_t bfrag[7][2];
            #pragma unroll
            for (int p = 0; p < 3; p++) {
                uint32_t row = warpN * 56 + p * 16 + (lane >> 4) * 8 + (lane & 7);
                uint32_t q   = kt * 2 + ((lane >> 3) & 1);
                uint32_t r4[4];
                ldsm4(r4, bS + swz(row, q));
                bfrag[2 * p][0] = r4[0]; bfrag[2 * p][1] = r4[1];
                bfrag[2 * p + 1][0] = r4[2]; bfrag[2 * p + 1][1] = r4[3];
            }
            {
                uint32_t row = warpN * 56 + 48 + (lane & 7);
                uint32_t q   = kt * 2 + ((lane >> 3) & 1);
                ldsm2(bfrag[6], bS + swz(row, q));
            }
            #pragma unroll
            for (int mi = 0; mi < 4; mi++)
                #pragma unroll
                for (int ni = 0; ni < 7; ni++)
                    mma16816(acc[mi][ni], afrag[mi], bfrag[ni]);
        }
    }

    // ---- epilogue: bias + split store ----
    const size_t regBase = (size_t)MDIM * NCLS;
    #pragma unroll
    for (int mi = 0; mi < 4; mi++) {
        #pragma unroll
        for (int ni = 0; ni < 7; ni++) {
            int m0 = mBlock + mi * 16 + (lane >> 2);
            int n0 = warpN * 56 + ni * 8 + (lane & 3) * 2;
            #pragma unroll
            for (int v = 0; v < 4; v++) {
                int m = m0 + (v >> 1) * 8;
                int n = n0 + (v & 1);
                if (n >= NTOT) continue;
                float val = acc[mi][ni][v] + bias_sm[n];
                if (n < NCLS) out[(size_t)m * NCLS + n] = val;
                else          out[regBase + (size_t)m * NREG + (n - NCLS)] = val;
            }
        }
    }
}

extern "C" void kernel_launch(void* const* d_in, const int* in_sizes, int n_in,
                              void* d_out, int out_size)
{
    const float* x  = (const float*)d_in[0];
    const float* Wc = (const float*)d_in[1];
    const float* bc = (const float*)d_in[2];
    const float* Wr = (const float*)d_in[3];
    const float* br = (const float*)d_in[4];
    float* out = (float*)d_out;

    cudaFuncSetAttribute(bbox_head_mma, cudaFuncAttributeMaxDynamicSharedMemorySize, SMEM_TOTAL);

    dim3 wgrid((KDIM / 4 + 255) / 256, NPAD);
    wconv_kernel<<<wgrid, 256>>>(Wc, Wr);

    bbox_head_mma<<<MDIM / BM, NTHREADS, SMEM_TOTAL>>>(x, bc, br, out);
}

// round 6
// speedup vs baseline: 1.2906x; 1.2906x over previous
#include <cuda_runtime.h>
#include <cuda_fp16.h>
#include <cstdint>

// ============================================================================
// BBoxHead as one fp16 legacy-HMMA GEMM (mma.sync.m16n8k16; compute_103 target
// has no tcgen05). C[8192,448] = A[8192,12544] x W[448,12544]^T, fp32 acc.
//   cols 0..80   -> cls head (+b_cls):  out[m*81 + n]
//   cols 81..404 -> reg head (+b_reg):  out[8192*81 + m*324 + (n-81)]
//   cols 405..447 = zero pad (discarded)
// Round-6 vs round-4 (339us, tensor=45%): BK 32 -> 64. Halves the per-chunk
// barrier/ramp exposure count (392 -> 196 chunks) that round-5 proved is the
// binding term (not smem). 16 warps, 2Mx8N warp grid, warp tile 32x56, 3-stage
// cp.async pipeline; both tiles 128B rows with XOR-8 swizzle.
// ============================================================================

#define KDIM  12544
#define MDIM  8192
#define NCLS  81
#define NREG  324
#define NTOT  405
#define NPAD  448
#define BM    64
#define BK    64
#define NCHUNK 196            // 12544 / 64
#define NTHREADS 512

#define A_STAGE 8192          // 64 rows x 128B
#define B_STAGE 57344         // 448 rows x 128B
#define OFF_BIAS 0
#define OFF_A    2048
#define OFF_B    (OFF_A + 3 * A_STAGE)        // 26624
#define SMEM_TOTAL (OFF_B + 3 * B_STAGE)      // 198656

__device__ __half g_Wh[(size_t)NPAD * KDIM];  // 11.2 MB fp16 W scratch

// ---------------- helpers ----------------
__device__ __forceinline__ uint32_t smem_u32(const void* p) {
    uint32_t a;
    asm("{ .reg .u64 t; cvta.to.shared.u64 t, %1; cvt.u32.u64 %0, t; }" : "=r"(a) : "l"(p));
    return a;
}
// 128B rows, 8 x 16B chunks per row; chunk XOR row&7 -> store phases (8 lanes
// covering one row) and ldmatrix phases (8 rows at fixed q) both conflict-free.
__device__ __forceinline__ uint32_t swz8(uint32_t row, uint32_t q) {
    return row * 128u + ((q ^ (row & 7u)) << 4);
}
__device__ __forceinline__ void cpa16(uint32_t dst, const void* src) {
    asm volatile("cp.async.cg.shared.global [%0], [%1], 16;" :: "r"(dst), "l"(src) : "memory");
}
#define CP_COMMIT() asm volatile("cp.async.commit_group;" ::: "memory")
#define CP_WAIT1()  asm volatile("cp.async.wait_group 1;" ::: "memory")

__device__ __forceinline__ void ldsm4(uint32_t* r, uint32_t addr) {
    asm volatile("ldmatrix.sync.aligned.m8n8.x4.shared.b16 {%0,%1,%2,%3}, [%4];"
        : "=r"(r[0]), "=r"(r[1]), "=r"(r[2]), "=r"(r[3]) : "r"(addr));
}
__device__ __forceinline__ void ldsm2(uint32_t* r, uint32_t addr) {
    asm volatile("ldmatrix.sync.aligned.m8n8.x2.shared.b16 {%0,%1}, [%2];"
        : "=r"(r[0]), "=r"(r[1]) : "r"(addr));
}
__device__ __forceinline__ void mma16816(float* c, const uint32_t* a, const uint32_t* b) {
    asm volatile(
        "mma.sync.aligned.m16n8k16.row.col.f32.f16.f16.f32 "
        "{%0,%1,%2,%3}, {%4,%5,%6,%7}, {%8,%9}, {%0,%1,%2,%3};"
        : "+f"(c[0]), "+f"(c[1]), "+f"(c[2]), "+f"(c[3])
        : "r"(a[0]), "r"(a[1]), "r"(a[2]), "r"(a[3]), "r"(b[0]), "r"(b[1]));
}
__device__ __forceinline__ uint32_t packh2(float lo, float hi) {
    uint32_t r;
    asm("cvt.rn.f16x2.f32 %0, %1, %2;" : "=r"(r) : "f"(hi), "f"(lo));
    return r;
}

// ---------------- W fp32 -> fp16 pre-kernel (rows >= 405 zeroed) ----------------
__global__ void wconv_kernel(const float* __restrict__ Wc, const float* __restrict__ Wr) {
    int row = blockIdx.y;
    int col = (blockIdx.x * 256 + threadIdx.x) * 4;
    if (col >= KDIM) return;
    float4 v = make_float4(0.f, 0.f, 0.f, 0.f);
    if (row < NCLS)      v = *reinterpret_cast<const float4*>(Wc + (size_t)row * KDIM + col);
    else if (row < NTOT) v = *reinterpret_cast<const float4*>(Wr + (size_t)(row - NCLS) * KDIM + col);
    *reinterpret_cast<uint2*>(&g_Wh[(size_t)row * KDIM + col]) =
        make_uint2(packh2(v.x, v.y), packh2(v.z, v.w));
}

// ---------------- main GEMM kernel ----------------
__global__ __launch_bounds__(NTHREADS, 1)
void bbox_head_mma(const float* __restrict__ A,
                   const float* __restrict__ bc,
                   const float* __restrict__ br,
                   float* __restrict__ out)
{
    extern __shared__ char smem[];
    const uint32_t sb = smem_u32(smem);
    const int tid   = threadIdx.x;
    const int lane  = tid & 31;
    const int wid   = tid >> 5;
    const int warpM = wid & 1;          // 0..1  (32-row halves of BM=64)
    const int warpN = wid >> 1;         // 0..7  (56-col slices of NPAD=448)
    const int mBlock = blockIdx.x * BM;
    float* bias_sm = reinterpret_cast<float*>(smem + OFF_BIAS);

    for (int j = tid; j < NPAD; j += NTHREADS)
        bias_sm[j] = (j < NCLS) ? bc[j] : ((j < NTOT) ? br[j - NCLS] : 0.f);

    // A loader role: every thread owns one 16B chunk: row (tid>>3), q (tid&7)
    const int ar = tid >> 3;            // 0..63
    const int aq = tid & 7;             // 0..7 (8 fp32 = 16B fp16)
    float4 abuf0, abuf1;

    float acc[2][7][4];
    #pragma unroll
    for (int i = 0; i < 2; i++)
        #pragma unroll
        for (int j = 0; j < 7; j++)
            #pragma unroll
            for (int v = 0; v < 4; v++) acc[i][j][v] = 0.f;

#define LDG_A(K0) do { \
        const float* _p = A + (size_t)(mBlock + ar) * KDIM + (K0) + aq * 8; \
        abuf0 = *reinterpret_cast<const float4*>(_p); \
        abuf1 = *reinterpret_cast<const float4*>(_p + 4); } while (0)

#define STS_A(S) do { \
        uint4 _v = make_uint4(packh2(abuf0.x, abuf0.y), packh2(abuf0.z, abuf0.w), \
                              packh2(abuf1.x, abuf1.y), packh2(abuf1.z, abuf1.w)); \
        *reinterpret_cast<uint4*>(smem + OFF_A + (S) * A_STAGE + swz8(ar, aq)) = _v; } while (0)

#define CP_B(K0, S) do { \
        _Pragma("unroll") \
        for (int _i = 0; _i < 7; _i++) { \
            int _idx = tid + _i * NTHREADS; /* 0..3583 = 448 rows x 8 chunks */ \
            int _row = _idx >> 3, _q = _idx & 7; \
            cpa16(sb + OFF_B + (S) * B_STAGE + swz8(_row, _q), \
                  g_Wh + (size_t)_row * KDIM + (K0) + _q * 8); } } while (0)

    // ---- prologue ----
    LDG_A(0);
    CP_B(0, 0); CP_COMMIT();
    STS_A(0);
    LDG_A(BK);
    CP_B(BK, 1); CP_COMMIT();

    // ---- main loop ----
    for (int k = 0; k < NCHUNK; k++) {
        CP_WAIT1();
        __syncthreads();

        if (k + 1 < NCHUNK) STS_A((k + 1) % 3);
        if (k + 2 < NCHUNK) { LDG_A((k + 2) * BK); CP_B((k + 2) * BK, (k + 2) % 3); }
        CP_COMMIT();

        const uint32_t aS = sb + OFF_A + (k % 3) * A_STAGE;
        const uint32_t bS = sb + OFF_B + (k % 3) * B_STAGE;

        #pragma unroll
        for (int kt = 0; kt < 4; kt++) {
            uint32_t afrag[2][4];
            #pragma unroll
            for (int msub = 0; msub < 2; msub++) {
                uint32_t row = warpM * 32 + msub * 16 + ((lane >> 3) & 1) * 8 + (lane & 7);
                uint32_t q   = kt * 2 + (lane >> 4);
                ldsm4(afrag[msub], aS + swz8(row, q));
            }
            uint32_t bfrag[7][2];
            #pragma unroll
            for (int p = 0; p < 3; p++) {
                uint32_t row = warpN * 56 + p * 16 + (lane >> 4) * 8 + (lane & 7);
                uint32_t q   = kt * 2 + ((lane >> 3) & 1);
                uint32_t r4[4];
                ldsm4(r4, bS + swz8(row, q));
                bfrag[2 * p][0] = r4[0]; bfrag[2 * p][1] = r4[1];
                bfrag[2 * p + 1][0] = r4[2]; bfrag[2 * p + 1][1] = r4[3];
            }
            {
                uint32_t row = warpN * 56 + 48 + (lane & 7);
                uint32_t q   = kt * 2 + ((lane >> 3) & 1);
                ldsm2(bfrag[6], bS + swz8(row, q));
            }
            #pragma unroll
            for (int mi = 0; mi < 2; mi++)
                #pragma unroll
                for (int ni = 0; ni < 7; ni++)
                    mma16816(acc[mi][ni], afrag[mi], bfrag[ni]);
        }
    }

    // ---- epilogue: bias + split store ----
    const size_t regBase = (size_t)MDIM * NCLS;
    #pragma unroll
    for (int mi = 0; mi < 2; mi++) {
        #pragma unroll
        for (int ni = 0; ni < 7; ni++) {
            int m0 = mBlock + warpM * 32 + mi * 16 + (lane >> 2);
            int n0 = warpN * 56 + ni * 8 + (lane & 3) * 2;
            #pragma unroll
            for (int v = 0; v < 4; v++) {
                int m = m0 + (v >> 1) * 8;
                int n = n0 + (v & 1);
                if (n >= NTOT) continue;
                float val = acc[mi][ni][v] + bias_sm[n];
                if (n < NCLS) out[(size_t)m * NCLS + n] = val;
                else          out[regBase + (size_t)m * NREG + (n - NCLS)] = val;
            }
        }
    }
}

extern "C" void kernel_launch(void* const* d_in, const int* in_sizes, int n_in,
                              void* d_out, int out_size)
{
    const float* x  = (const float*)d_in[0];
    const float* Wc = (const float*)d_in[1];
    const float* bc = (const float*)d_in[2];
    const float* Wr = (const float*)d_in[3];
    const float* br = (const float*)d_in[4];
    float* out = (float*)d_out;

    cudaFuncSetAttribute(bbox_head_mma, cudaFuncAttributeMaxDynamicSharedMemorySize, SMEM_TOTAL);

    dim3 wgrid((KDIM / 4 + 255) / 256, NPAD);
    wconv_kernel<<<wgrid, 256>>>(Wc, Wr);

    bbox_head_mma<<<MDIM / BM, NTHREADS, SMEM_TOTAL>>>(x, bc, br, out);
}